// round 7
// baseline (speedup 1.0000x reference)
#include <cuda_runtime.h>
#include <cuda_fp16.h>
#include <math.h>
#include <stdint.h>

#define NROWS 4096
#define TWO_N 8192
#define D 128
#define NTILE 64
#define NJOBS 2080                  // 64*65/2 triangle tiles
#define GRID_MAIN 148
#define K2C 14.4269504088896340f    // 10 / ln(2)
#define PSC 3.798282565009841f      // sqrt(10/ln(2)) pre-scale

// ---------------- device scratch (allocation-free) ----------------
__device__ uint8_t        g_f8[TWO_N * D];     // e4m3, sqrt(K2C)-scaled normalized reps
__device__ float          g_pos[TWO_N];
__device__ float          g_part[NTILE * NTILE * 128];
__device__ float          g_bsum[32];
__device__ unsigned int   g_cnt;               // zero-init; self-resetting

// ---------------- smem map (dynamic): fp8 tiles are 16KB ----------------
#define SM_A      0
#define SM_B(s)   (16384 + (s) * 16384)
#define SM_ROWRED 49152
#define SM_COLRED 51200
#define SMEM_BYTES 52224

// ---------------- helpers ----------------
__device__ __forceinline__ uint32_t smem_u32(const void* p) {
    uint32_t a;
    asm("{ .reg .u64 t; cvta.to.shared.u64 t, %1; cvt.u32.u64 %0, t; }" : "=r"(a) : "l"(p));
    return a;
}
__device__ __forceinline__ float ex2f(float x) {
    float r; asm("ex2.approx.ftz.f32 %0, %1;" : "=f"(r) : "f"(x)); return r;
}
__device__ __forceinline__ uint32_t pack_e4m3x4(float x, float y, float z, float w) {
    uint32_t r;
    asm("{ .reg .b16 h0, h1;\n\t"
        "cvt.rn.satfinite.e4m3x2.f32 h0, %2, %1;\n\t"   // h0 = {hi=y, lo=x}
        "cvt.rn.satfinite.e4m3x2.f32 h1, %4, %3;\n\t"   // h1 = {hi=w, lo=z}
        "mov.b32 %0, {h0, h1}; }"
        : "=r"(r) : "f"(x), "f"(y), "f"(z), "f"(w));
    return r;
}
__device__ __forceinline__ void ldsm4(uint32_t* r, uint32_t addr) {
    asm volatile("ldmatrix.sync.aligned.m8n8.x4.shared.b16 {%0,%1,%2,%3}, [%4];"
                 : "=r"(r[0]), "=r"(r[1]), "=r"(r[2]), "=r"(r[3]) : "r"(addr));
}
__device__ __forceinline__ void mma_fp8(float* d, const uint32_t* a, uint32_t b0, uint32_t b1) {
    asm volatile("mma.sync.aligned.m16n8k32.row.col.f32.e4m3.e4m3.f32 "
                 "{%0,%1,%2,%3}, {%4,%5,%6,%7}, {%8,%9}, {%0,%1,%2,%3};"
                 : "+f"(d[0]), "+f"(d[1]), "+f"(d[2]), "+f"(d[3])
                 : "r"(a[0]), "r"(a[1]), "r"(a[2]), "r"(a[3]), "r"(b0), "r"(b1));
}
#define CP_ASYNC16(sa, ga) \
    asm volatile("cp.async.cg.shared.global [%0], [%1], 16;" :: "r"(sa), "l"(ga))
#define CP_COMMIT() asm volatile("cp.async.commit_group;" ::: "memory")
#define CP_WAIT1()  asm volatile("cp.async.wait_group 1;" ::: "memory")

__device__ __forceinline__ void job_ij(int g, int& I, int& J) {
    int i = 0, off = 0;
    while (off + (NTILE - i) <= g) { off += NTILE - i; i++; }
    I = i; J = i + (g - off);
}
__device__ __forceinline__ void job_adv(int& I, int& J) {
    if (++J == NTILE) { ++I; J = I; }
}

// ---------------------------------------------------------------------------
// Kernel 1: normalize pair rows (r, r+N), sqrt(K2C) pre-scale, e4m3 cast,
// fp32-exact positive sims. One warp per pair.
// ---------------------------------------------------------------------------
__global__ void k_prep(const float* __restrict__ zi, const float* __restrict__ zj) {
    int warp = threadIdx.x >> 5, lane = threadIdx.x & 31;
    int p = blockIdx.x * 8 + warp;
    float4 a = ((const float4*)(zi + (size_t)p * D))[lane];
    float4 b = ((const float4*)(zj + (size_t)p * D))[lane];
    float sa = a.x*a.x + a.y*a.y + a.z*a.z + a.w*a.w;
    float sb = b.x*b.x + b.y*b.y + b.z*b.z + b.w*b.w;
    float dp = a.x*b.x + a.y*b.y + a.z*b.z + a.w*b.w;
    #pragma unroll
    for (int o = 16; o; o >>= 1) {
        sa += __shfl_xor_sync(0xffffffffu, sa, o);
        sb += __shfl_xor_sync(0xffffffffu, sb, o);
        dp += __shfl_xor_sync(0xffffffffu, dp, o);
    }
    float ia = 1.0f / fmaxf(sqrtf(sa), 1e-8f);
    float ib = 1.0f / fmaxf(sqrtf(sb), 1e-8f);
    if (lane == 0) {
        float pos = dp * ia * ib;
        g_pos[p] = pos;
        g_pos[p + NROWS] = pos;
    }
    float fa = ia * PSC, fb = ib * PSC;
    uint32_t pa = pack_e4m3x4(a.x*fa, a.y*fa, a.z*fa, a.w*fa);
    uint32_t pb = pack_e4m3x4(b.x*fb, b.y*fb, b.z*fb, b.w*fb);
    *(uint32_t*)(g_f8 + (size_t)p * D + lane * 4)           = pa;
    *(uint32_t*)(g_f8 + (size_t)(p + NROWS) * D + lane * 4) = pb;
}

// ---------------------------------------------------------------------------
// tile loaders: 128 rows x 128 fp8 bytes (128B rows = 8 x 16B chunks), XOR swizzle
// ---------------------------------------------------------------------------
__device__ __forceinline__ void load_B_async(uint32_t sb, uint32_t off, int rowBase, int t) {
    #pragma unroll
    for (int rep = 0; rep < 4; rep++) {
        int idx = rep * 256 + t;          // 0..1023
        int row = idx >> 3, ch = idx & 7;
        uint32_t so = off + (uint32_t)(row * 128) + ((uint32_t)(ch ^ (row & 7)) << 4);
        CP_ASYNC16(sb + so, g_f8 + (size_t)(rowBase + row) * D + ch * 16);
    }
}
__device__ __forceinline__ void load_A_plain(char* sm, int rowBase, int t) {
    #pragma unroll
    for (int rep = 0; rep < 4; rep++) {
        int idx = rep * 256 + t;
        int row = idx >> 3, ch = idx & 7;
        uint32_t so = (uint32_t)(row * 128) + ((uint32_t)(ch ^ (row & 7)) << 4);
        *(uint4*)(sm + SM_A + so) = *(const uint4*)(g_f8 + (size_t)(rowBase + row) * D + ch * 16);
    }
}

// ---------------------------------------------------------------------------
// Kernel 2: triangle sim-GEMM (e4m3 fp8, k32) + exp row/col sums.
// 148 CTAs, even job split; 256 threads = 2x4 warps, warp tile 64x32.
// Diagonal tiles substitute the exactly-known e^0 = 1 on row==col.
// ---------------------------------------------------------------------------
__global__ __launch_bounds__(256, 1)
void k_main() {
    extern __shared__ char sm[];
    const uint32_t sb = smem_u32(sm);
    const int t = threadIdx.x, lane = t & 31, wid = t >> 5;
    const int warpM = wid >> 2, warpN = wid & 3;

    const int jb = (int)(((long)blockIdx.x * NJOBS) / GRID_MAIN);
    const int je = (int)(((long)(blockIdx.x + 1) * NJOBS) / GRID_MAIN);
    const int njobs = je - jb;

    int Ic, Jc; job_ij(jb, Ic, Jc);
    int Ip = Ic, Jp = Jc;

    load_B_async(sb, SM_B(0), Jp * 128, t); CP_COMMIT(); job_adv(Ip, Jp);
    load_B_async(sb, SM_B(1), Jp * 128, t); CP_COMMIT(); job_adv(Ip, Jp);

    const int r7   = lane & 7;
    const int rowA = (lane & 7) + ((lane >> 3) & 1) * 8;  const int c4A = lane >> 4;
    const int rowB = (lane & 7) + ((lane >> 4) << 3);     const int c4B = (lane >> 3) & 1;

    uint32_t aRow[4];
    #pragma unroll
    for (int mt = 0; mt < 4; mt++)
        aRow[mt] = sb + SM_A + (uint32_t)((warpM * 64 + mt * 16 + rowA) * 128);
    uint32_t bRow[2];
    #pragma unroll
    for (int g = 0; g < 2; g++) bRow[g] = (uint32_t)((warpN * 32 + g * 16 + rowB) * 128);

    // epilogue lane coordinates (within 128x128 tile)
    const int rq = lane >> 2;          // + mt*16 + 8*(q>>1) + warpM*64
    const int cq = (lane & 3) * 2;     // + nt*8 + (q&1) + warpN*32

    float* rowred = (float*)(sm + SM_ROWRED);
    float* colred = (float*)(sm + SM_COLRED);
    int Ia = -1;

    for (int jj = 0; jj < njobs; jj++) {
        if (Ic != Ia) { load_A_plain(sm, Ic * 128, t); Ia = Ic; }
        CP_WAIT1();
        __syncthreads();

        const uint32_t bBase = sb + SM_B(jj & 1);

        float d[4][4][4];
        #pragma unroll
        for (int mt = 0; mt < 4; mt++)
            #pragma unroll
            for (int nt = 0; nt < 4; nt++)
                #pragma unroll
                for (int q = 0; q < 4; q++) d[mt][nt][q] = -K2C;  // folds the -10 shift

        #pragma unroll
        for (int ks = 0; ks < 4; ks++) {      // K=128 / 32 per mma
            uint32_t ah[4][4], bh[8];
            const uint32_t offA = (uint32_t)(((2 * ks + c4A) ^ r7) << 4);
            const uint32_t offB = (uint32_t)(((2 * ks + c4B) ^ r7) << 4);
            #pragma unroll
            for (int mt = 0; mt < 4; mt++) ldsm4(ah[mt], aRow[mt] + offA);
            #pragma unroll
            for (int g = 0; g < 2; g++) ldsm4(bh + g * 4, bBase + bRow[g] + offB);
            #pragma unroll
            for (int mt = 0; mt < 4; mt++)
                #pragma unroll
                for (int nt = 0; nt < 4; nt++)
                    mma_fp8(d[mt][nt], ah[mt], bh[nt * 2], bh[nt * 2 + 1]);
        }
        __syncthreads();
        if (jj + 2 < njobs) {
            load_B_async(sb, SM_B(jj & 1), Jp * 128, t); CP_COMMIT(); job_adv(Ip, Jp);
        } else {
            CP_COMMIT();
        }

        // ---- epilogue: exp + row sums + col sums (d = 10*sim/ln2 - 10/ln2) ----
        float rs[8], cc[8];
        #pragma unroll
        for (int u = 0; u < 8; u++) { rs[u] = 0.0f; cc[u] = 0.0f; }

        if (Ic != Jc) {
            #pragma unroll
            for (int mt = 0; mt < 4; mt++) {
                #pragma unroll
                for (int nt = 0; nt < 4; nt++) {
                    float e0 = ex2f(d[mt][nt][0]);
                    float e1 = ex2f(d[mt][nt][1]);
                    float e2 = ex2f(d[mt][nt][2]);
                    float e3 = ex2f(d[mt][nt][3]);
                    rs[mt * 2 + 0] += e0 + e1;
                    rs[mt * 2 + 1] += e2 + e3;
                    cc[nt * 2 + 0] += e0 + e2;
                    cc[nt * 2 + 1] += e1 + e3;
                }
            }
        } else {
            // diagonal tile: substitute exact 1.0 where global row == col
            #pragma unroll
            for (int mt = 0; mt < 4; mt++) {
                const int r0 = warpM * 64 + mt * 16 + rq;      // q>>1 == 0
                const int r1 = r0 + 8;                          // q>>1 == 1
                #pragma unroll
                for (int nt = 0; nt < 4; nt++) {
                    const int c0 = warpN * 32 + nt * 8 + cq;   // q&1 == 0
                    const int c1 = c0 + 1;                      // q&1 == 1
                    float e0 = (r0 == c0) ? 1.0f : ex2f(d[mt][nt][0]);
                    float e1 = (r0 == c1) ? 1.0f : ex2f(d[mt][nt][1]);
                    float e2 = (r1 == c0) ? 1.0f : ex2f(d[mt][nt][2]);
                    float e3 = (r1 == c1) ? 1.0f : ex2f(d[mt][nt][3]);
                    rs[mt * 2 + 0] += e0 + e1;
                    rs[mt * 2 + 1] += e2 + e3;
                    cc[nt * 2 + 0] += e0 + e2;
                    cc[nt * 2 + 1] += e1 + e3;
                }
            }
        }
        #pragma unroll
        for (int u = 0; u < 8; u++) {
            float v = rs[u];
            v += __shfl_xor_sync(0xffffffffu, v, 1);
            v += __shfl_xor_sync(0xffffffffu, v, 2);
            if ((lane & 3) == 0) {
                int r = warpM * 64 + (u >> 1) * 16 + (u & 1) * 8 + (lane >> 2);
                rowred[r * 4 + warpN] = v;
            }
        }
        #pragma unroll
        for (int u = 0; u < 8; u++) {
            float v = cc[u];
            v += __shfl_xor_sync(0xffffffffu, v, 4);
            v += __shfl_xor_sync(0xffffffffu, v, 8);
            v += __shfl_xor_sync(0xffffffffu, v, 16);
            if (lane < 4) {
                int c = warpN * 32 + (u >> 1) * 8 + (lane & 3) * 2 + (u & 1);
                colred[c * 2 + warpM] = v;
            }
        }
        __syncthreads();
        if (t < 128) {
            float s = rowred[t * 4] + rowred[t * 4 + 1] + rowred[t * 4 + 2] + rowred[t * 4 + 3];
            g_part[(size_t)((Ic << 6) + Jc) * 128 + t] = s;
        } else if (Jc > Ic) {
            int c = t - 128;
            g_part[(size_t)((Jc << 6) + Ic) * 128 + c] = colred[c * 2] + colred[c * 2 + 1];
        }
        __syncthreads();
        job_adv(Ic, Jc);
    }
}

// ---------------------------------------------------------------------------
// Kernel 3: per-row loss + full reduction (last-block-done pattern).
// ---------------------------------------------------------------------------
__global__ void k_tail(float* __restrict__ out) {
    __shared__ float red[256];
    __shared__ bool isLast;
    int r = blockIdx.x * 256 + threadIdx.x;
    int I = r >> 7, rr = r & 127;
    float S = 0.0f;
    const float* base = g_part + (size_t)(I << 6) * 128 + rr;
    #pragma unroll 8
    for (int J = 0; J < NTILE; J++) S += base[(size_t)J * 128];
    float p = g_pos[r];
    float Sf = S + expf(fmaf(10.0f, p, -10.0f));
    red[threadIdx.x] = logf(Sf) + 10.0f - 10.0f * p;
    __syncthreads();
    for (int s = 128; s; s >>= 1) {
        if (threadIdx.x < s) red[threadIdx.x] += red[threadIdx.x + s];
        __syncthreads();
    }
    if (threadIdx.x == 0) {
        g_bsum[blockIdx.x] = red[0];
        __threadfence();
        unsigned int done = atomicAdd(&g_cnt, 1u);
        isLast = (done == 31u);
    }
    __syncthreads();
    if (isLast && threadIdx.x == 0) {
        float acc = 0.0f;
        #pragma unroll
        for (int b = 0; b < 32; b++) acc += ((volatile float*)g_bsum)[b];
        out[0] = acc * (1.0f / (float)TWO_N);
        g_cnt = 0;   // self-reset for next graph replay
    }
}

// ---------------------------------------------------------------------------
extern "C" void kernel_launch(void* const* d_in, const int* in_sizes, int n_in,
                              void* d_out, int out_size) {
    const float* zi = (const float*)d_in[0];
    const float* zj = (const float*)d_in[1];
    float* out = (float*)d_out;

    cudaFuncSetAttribute(k_main, cudaFuncAttributeMaxDynamicSharedMemorySize, SMEM_BYTES);

    k_prep<<<NROWS / 8, 256>>>(zi, zj);
    k_main<<<GRID_MAIN, 256, SMEM_BYTES>>>();
    k_tail<<<32, 256>>>(out);
}